// round 6
// baseline (speedup 1.0000x reference)
#include <cuda_runtime.h>
#include <cuda_bf16.h>
#include <math.h>

// Problem constants (from reference): B=16, S=4096, E=2048, WIN=64
#define PB 16
#define PS 4096
#define PE 2048
#define TPB 16          // tokens per block in kernel 1
#define CHUNK 512       // windows per block in kernel 2
#define NCHUNK ((PS + CHUNK - 1) / CHUNK)   // 8

// Scratch (allocation-free rule: __device__ globals)
__device__ float g_s[PB * PS];
__device__ float g_bmax[PB * NCHUNK];

// ---------------------------------------------------------------------------
// Kernel 1: per-token dot product + bias + mask. 256 threads, TPB tokens per
// block. Thread t owns element slots [t*4..t*4+3] and [1024+t*4..], so its W
// chunk (w0,w1) is invariant across tokens -> registers, loaded once.
// x loads fully coalesced float4; 2*TPB independent LDG.128 per thread.
// ---------------------------------------------------------------------------
__global__ void __launch_bounds__(256)
dot_mask_kernel(const float* __restrict__ x,
                const unsigned int* __restrict__ mask,
                const float* __restrict__ W,
                const float* __restrict__ bias)
{
    const int tok0 = blockIdx.x * TPB;
    const int t = threadIdx.x;
    const int warp = t >> 5;
    const int lane = t & 31;

    const float4* __restrict__ W4 = reinterpret_cast<const float4*>(W);
    const float4 w0 = W4[t];
    const float4 w1 = W4[t + 256];

    const float4* __restrict__ xr =
        reinterpret_cast<const float4*>(x) + (size_t)tok0 * (PE / 4);

    __shared__ float wsum[TPB * 8];

    #pragma unroll
    for (int i = 0; i < TPB; i++) {
        float4 a0 = xr[(size_t)i * (PE / 4) + t];
        float4 a1 = xr[(size_t)i * (PE / 4) + t + 256];

        float acc = a0.x * w0.x + a0.y * w0.y + a0.z * w0.z + a0.w * w0.w
                  + a1.x * w1.x + a1.y * w1.y + a1.z * w1.z + a1.w * w1.w;

        #pragma unroll
        for (int o = 16; o > 0; o >>= 1)
            acc += __shfl_xor_sync(0xFFFFFFFFu, acc, o);

        if (lane == 0) wsum[i * 8 + warp] = acc;
    }
    __syncthreads();

    if (t < TPB) {
        float v = 0.0f;
        #pragma unroll
        for (int j = 0; j < 8; j++) v += wsum[t * 8 + j];
        const int token = tok0 + t;
        g_s[token] = (mask[token] != 0u) ? (v + bias[0]) : 0.0f;
    }
}

// ---------------------------------------------------------------------------
// Kernel 2: per-chunk sliding-window partial max.
// grid = (NCHUNK, PB); block = 256 threads handles CHUNK=512 windows.
// Chunk data (512 + win - 1 elems) staged in smem; each thread computes two
// window sums directly (unrolled for win==64), block max-reduce -> g_bmax.
// ---------------------------------------------------------------------------
__global__ void __launch_bounds__(256)
wmax_partial_kernel(const int* __restrict__ win_ptr)
{
    const int c = blockIdx.x;
    const int b = blockIdx.y;
    const int tid = threadIdx.x;
    const int win = *win_ptr;
    const int nwin = PS - win + 1;
    const int base = c * CHUNK;

    __shared__ float sm[CHUNK + 512];   // supports win <= 513
    const float* __restrict__ sr = g_s + (size_t)b * PS;

    float best = -INFINITY;

    if (win <= 512) {
        int need = CHUNK + win - 1;
        int avail = PS - base;
        if (need > avail) need = avail;
        for (int i = tid; i < need; i += 256)
            sm[i] = sr[base + i];
        __syncthreads();

        if (win == 64) {
            #pragma unroll
            for (int r = 0; r < CHUNK / 256; r++) {
                int w = tid + r * 256;
                if (base + w < nwin) {
                    float s = 0.0f;
                    #pragma unroll
                    for (int k = 0; k < 64; k++) s += sm[w + k];
                    best = fmaxf(best, s);
                }
            }
        } else {
            for (int r = 0; r < CHUNK / 256; r++) {
                int w = tid + r * 256;
                if (base + w < nwin) {
                    float s = 0.0f;
                    for (int k = 0; k < win; k++) s += sm[w + k];
                    best = fmaxf(best, s);
                }
            }
        }
    } else {
        // generic fallback: read directly from global (rare path)
        for (int r = 0; r < CHUNK / 256; r++) {
            int w = tid + r * 256;
            if (base + w < nwin) {
                float s = 0.0f;
                for (int k = 0; k < win; k++) s += sr[base + w + k];
                best = fmaxf(best, s);
            }
        }
    }

    // block max reduce
    #pragma unroll
    for (int o = 16; o > 0; o >>= 1)
        best = fmaxf(best, __shfl_xor_sync(0xFFFFFFFFu, best, o));

    __shared__ float wmax[8];
    if ((tid & 31) == 0) wmax[tid >> 5] = best;
    __syncthreads();

    if (tid < 8) {
        float v = wmax[tid];
        #pragma unroll
        for (int o = 4; o > 0; o >>= 1)
            v = fmaxf(v, __shfl_xor_sync(0x000000FFu, v, o));
        if (tid == 0) g_bmax[b * NCHUNK + c] = v;
    }
}

// ---------------------------------------------------------------------------
// Kernel 3: final reduce over NCHUNK partials per batch, divide by win.
// ---------------------------------------------------------------------------
__global__ void __launch_bounds__(32)
final_kernel(float* __restrict__ out, const int* __restrict__ win_ptr)
{
    const int t = threadIdx.x;
    const float win = (float)(*win_ptr);
    if (t < PB) {
        float m = -INFINITY;
        #pragma unroll
        for (int j = 0; j < NCHUNK; j++)
            m = fmaxf(m, g_bmax[t * NCHUNK + j]);
        out[t] = m / win;
    }
}

// ---------------------------------------------------------------------------
// Launch: inputs in order x, mask, W, b, window_size
// ---------------------------------------------------------------------------
extern "C" void kernel_launch(void* const* d_in, const int* in_sizes, int n_in,
                              void* d_out, int out_size)
{
    const float*        x    = (const float*)d_in[0];
    const unsigned int* mask = (const unsigned int*)d_in[1];
    const float*        W    = (const float*)d_in[2];
    const float*        bias = (const float*)d_in[3];
    const int*          win  = (const int*)d_in[4];
    float* out = (float*)d_out;

    dot_mask_kernel<<<(PB * PS) / TPB, 256>>>(x, mask, W, bias);

    dim3 g2(NCHUNK, PB);
    wmax_partial_kernel<<<g2, 256>>>(win);

    final_kernel<<<1, 32>>>(out, win);
}

// round 7
// speedup vs baseline: 1.0145x; 1.0145x over previous
#include <cuda_runtime.h>
#include <cuda_bf16.h>
#include <math.h>

// Problem constants (from reference): B=16, S=4096, E=2048, WIN=64
#define PB 16
#define PS 4096
#define PE 2048
#define TPB 16          // tokens per block in kernel 1
#define CHUNK 512       // windows per block in kernel 2
#define NCHUNK ((PS + CHUNK - 1) / CHUNK)   // 8

// Scratch (allocation-free rule: __device__ globals)
__device__ float g_s[PB * PS];
__device__ float g_bmax[PB * NCHUNK];

// ---------------------------------------------------------------------------
// Kernel 1: per-token dot product + bias + mask. 256 threads, TPB tokens per
// block. Thread t owns element slots [t*4..t*4+3] and [1024+t*4..], so its W
// chunk (w0,w1) is invariant across tokens -> registers, loaded once.
// x loads fully coalesced float4; 2*TPB independent LDG.128 per thread.
// ---------------------------------------------------------------------------
__global__ void __launch_bounds__(256)
dot_mask_kernel(const float* __restrict__ x,
                const unsigned int* __restrict__ mask,
                const float* __restrict__ W,
                const float* __restrict__ bias)
{
    const int tok0 = blockIdx.x * TPB;
    const int t = threadIdx.x;
    const int warp = t >> 5;
    const int lane = t & 31;

    const float4* __restrict__ W4 = reinterpret_cast<const float4*>(W);
    const float4 w0 = W4[t];
    const float4 w1 = W4[t + 256];

    const float4* __restrict__ xr =
        reinterpret_cast<const float4*>(x) + (size_t)tok0 * (PE / 4);

    __shared__ float wsum[TPB * 8];

    #pragma unroll
    for (int i = 0; i < TPB; i++) {
        float4 a0 = xr[(size_t)i * (PE / 4) + t];
        float4 a1 = xr[(size_t)i * (PE / 4) + t + 256];

        float acc = a0.x * w0.x + a0.y * w0.y + a0.z * w0.z + a0.w * w0.w
                  + a1.x * w1.x + a1.y * w1.y + a1.z * w1.z + a1.w * w1.w;

        #pragma unroll
        for (int o = 16; o > 0; o >>= 1)
            acc += __shfl_xor_sync(0xFFFFFFFFu, acc, o);

        if (lane == 0) wsum[i * 8 + warp] = acc;
    }
    __syncthreads();

    if (t < TPB) {
        float v = 0.0f;
        #pragma unroll
        for (int j = 0; j < 8; j++) v += wsum[t * 8 + j];
        const int token = tok0 + t;
        g_s[token] = (mask[token] != 0u) ? (v + bias[0]) : 0.0f;
    }
}

// ---------------------------------------------------------------------------
// Kernel 2: per-chunk sliding-window partial max.
// grid = (NCHUNK, PB); block = 256 threads handles CHUNK=512 windows.
// Chunk data (512 + win - 1 elems) staged in smem; each thread computes two
// window sums directly (unrolled for win==64), block max-reduce -> g_bmax.
// ---------------------------------------------------------------------------
__global__ void __launch_bounds__(256)
wmax_partial_kernel(const int* __restrict__ win_ptr)
{
    const int c = blockIdx.x;
    const int b = blockIdx.y;
    const int tid = threadIdx.x;
    const int win = *win_ptr;
    const int nwin = PS - win + 1;
    const int base = c * CHUNK;

    __shared__ float sm[CHUNK + 512];   // supports win <= 513
    const float* __restrict__ sr = g_s + (size_t)b * PS;

    float best = -INFINITY;

    if (win <= 512) {
        int need = CHUNK + win - 1;
        int avail = PS - base;
        if (need > avail) need = avail;
        for (int i = tid; i < need; i += 256)
            sm[i] = sr[base + i];
        __syncthreads();

        if (win == 64) {
            #pragma unroll
            for (int r = 0; r < CHUNK / 256; r++) {
                int w = tid + r * 256;
                if (base + w < nwin) {
                    float s = 0.0f;
                    #pragma unroll
                    for (int k = 0; k < 64; k++) s += sm[w + k];
                    best = fmaxf(best, s);
                }
            }
        } else {
            for (int r = 0; r < CHUNK / 256; r++) {
                int w = tid + r * 256;
                if (base + w < nwin) {
                    float s = 0.0f;
                    for (int k = 0; k < win; k++) s += sm[w + k];
                    best = fmaxf(best, s);
                }
            }
        }
    } else {
        // generic fallback: read directly from global (rare path)
        for (int r = 0; r < CHUNK / 256; r++) {
            int w = tid + r * 256;
            if (base + w < nwin) {
                float s = 0.0f;
                for (int k = 0; k < win; k++) s += sr[base + w + k];
                best = fmaxf(best, s);
            }
        }
    }

    // block max reduce
    #pragma unroll
    for (int o = 16; o > 0; o >>= 1)
        best = fmaxf(best, __shfl_xor_sync(0xFFFFFFFFu, best, o));

    __shared__ float wmax[8];
    if ((tid & 31) == 0) wmax[tid >> 5] = best;
    __syncthreads();

    if (tid < 8) {
        float v = wmax[tid];
        #pragma unroll
        for (int o = 4; o > 0; o >>= 1)
            v = fmaxf(v, __shfl_xor_sync(0x000000FFu, v, o));
        if (tid == 0) g_bmax[b * NCHUNK + c] = v;
    }
}

// ---------------------------------------------------------------------------
// Kernel 3: final reduce over NCHUNK partials per batch, divide by win.
// ---------------------------------------------------------------------------
__global__ void __launch_bounds__(32)
final_kernel(float* __restrict__ out, const int* __restrict__ win_ptr)
{
    const int t = threadIdx.x;
    const float win = (float)(*win_ptr);
    if (t < PB) {
        float m = -INFINITY;
        #pragma unroll
        for (int j = 0; j < NCHUNK; j++)
            m = fmaxf(m, g_bmax[t * NCHUNK + j]);
        out[t] = m / win;
    }
}

// ---------------------------------------------------------------------------
// Launch: inputs in order x, mask, W, b, window_size
// ---------------------------------------------------------------------------
extern "C" void kernel_launch(void* const* d_in, const int* in_sizes, int n_in,
                              void* d_out, int out_size)
{
    const float*        x    = (const float*)d_in[0];
    const unsigned int* mask = (const unsigned int*)d_in[1];
    const float*        W    = (const float*)d_in[2];
    const float*        bias = (const float*)d_in[3];
    const int*          win  = (const int*)d_in[4];
    float* out = (float*)d_out;

    dot_mask_kernel<<<(PB * PS) / TPB, 256>>>(x, mask, W, bias);

    dim3 g2(NCHUNK, PB);
    wmax_partial_kernel<<<g2, 256>>>(win);

    final_kernel<<<1, 32>>>(out, win);
}

// round 8
// speedup vs baseline: 1.0160x; 1.0015x over previous
#include <cuda_runtime.h>
#include <cuda_bf16.h>
#include <math.h>

// Problem constants (from reference): B=16, S=4096, E=2048, WIN=64
#define PB 16
#define PS 4096
#define PE 2048
#define TPB 16          // tokens per batch in kernel 1
#define NBATCH ((PB * PS) / TPB)            // 4096 token-batches
#define GRID1 592       // 148 SMs * 4 CTAs -> single persistent wave
#define CHUNK 512       // windows per block in kernel 2
#define NCHUNK ((PS + CHUNK - 1) / CHUNK)   // 8

// Scratch (allocation-free rule: __device__ globals)
__device__ float g_s[PB * PS];
__device__ float g_bmax[PB * NCHUNK];

// ---------------------------------------------------------------------------
// Kernel 1: per-token dot product + bias + mask. Persistent grid-stride over
// token-batches (GRID1 CTAs = one wave on 148 SMs -> no wave-transition idle).
// 256 threads; thread t owns element slots [t*4..t*4+3] and [1024+t*4..], so
// its W chunk (w0,w1) is register-resident, loaded once per CTA.
// x loads fully coalesced float4; 32 independent LDG.128 per thread per batch.
// ---------------------------------------------------------------------------
__global__ void __launch_bounds__(256)
dot_mask_kernel(const float* __restrict__ x,
                const unsigned int* __restrict__ mask,
                const float* __restrict__ W,
                const float* __restrict__ bias)
{
    const int t = threadIdx.x;
    const int warp = t >> 5;
    const int lane = t & 31;

    const float4* __restrict__ W4 = reinterpret_cast<const float4*>(W);
    const float4 w0 = W4[t];
    const float4 w1 = W4[t + 256];
    const float bv = bias[0];

    __shared__ float wsum[TPB * 8];

    for (int batch = blockIdx.x; batch < NBATCH; batch += GRID1) {
        const int tok0 = batch * TPB;
        const float4* __restrict__ xr =
            reinterpret_cast<const float4*>(x) + (size_t)tok0 * (PE / 4);

        #pragma unroll
        for (int i = 0; i < TPB; i++) {
            float4 a0 = xr[(size_t)i * (PE / 4) + t];
            float4 a1 = xr[(size_t)i * (PE / 4) + t + 256];

            float acc = a0.x * w0.x + a0.y * w0.y + a0.z * w0.z + a0.w * w0.w
                      + a1.x * w1.x + a1.y * w1.y + a1.z * w1.z + a1.w * w1.w;

            #pragma unroll
            for (int o = 16; o > 0; o >>= 1)
                acc += __shfl_xor_sync(0xFFFFFFFFu, acc, o);

            if (lane == 0) wsum[i * 8 + warp] = acc;
        }
        __syncthreads();

        if (t < TPB) {
            float v = 0.0f;
            #pragma unroll
            for (int j = 0; j < 8; j++) v += wsum[t * 8 + j];
            const int token = tok0 + t;
            g_s[token] = (mask[token] != 0u) ? (v + bv) : 0.0f;
        }
        __syncthreads();
    }
}

// ---------------------------------------------------------------------------
// Kernel 2: per-chunk sliding-window partial max.
// grid = (NCHUNK, PB); block = 256 threads handles CHUNK=512 windows.
// Chunk data (512 + win - 1 elems) staged in smem; each thread computes two
// window sums directly (unrolled for win==64), block max-reduce -> g_bmax.
// ---------------------------------------------------------------------------
__global__ void __launch_bounds__(256)
wmax_partial_kernel(const int* __restrict__ win_ptr)
{
    const int c = blockIdx.x;
    const int b = blockIdx.y;
    const int tid = threadIdx.x;
    const int win = *win_ptr;
    const int nwin = PS - win + 1;
    const int base = c * CHUNK;

    __shared__ float sm[CHUNK + 512];   // supports win <= 513
    const float* __restrict__ sr = g_s + (size_t)b * PS;

    float best = -INFINITY;

    if (win <= 512) {
        int need = CHUNK + win - 1;
        int avail = PS - base;
        if (need > avail) need = avail;
        for (int i = tid; i < need; i += 256)
            sm[i] = sr[base + i];
        __syncthreads();

        if (win == 64) {
            #pragma unroll
            for (int r = 0; r < CHUNK / 256; r++) {
                int w = tid + r * 256;
                if (base + w < nwin) {
                    float s = 0.0f;
                    #pragma unroll
                    for (int k = 0; k < 64; k++) s += sm[w + k];
                    best = fmaxf(best, s);
                }
            }
        } else {
            for (int r = 0; r < CHUNK / 256; r++) {
                int w = tid + r * 256;
                if (base + w < nwin) {
                    float s = 0.0f;
                    for (int k = 0; k < win; k++) s += sm[w + k];
                    best = fmaxf(best, s);
                }
            }
        }
    } else {
        // generic fallback: read directly from global (rare path)
        for (int r = 0; r < CHUNK / 256; r++) {
            int w = tid + r * 256;
            if (base + w < nwin) {
                float s = 0.0f;
                for (int k = 0; k < win; k++) s += sr[base + w + k];
                best = fmaxf(best, s);
            }
        }
    }

    // block max reduce
    #pragma unroll
    for (int o = 16; o > 0; o >>= 1)
        best = fmaxf(best, __shfl_xor_sync(0xFFFFFFFFu, best, o));

    __shared__ float wmax[8];
    if ((tid & 31) == 0) wmax[tid >> 5] = best;
    __syncthreads();

    if (tid < 8) {
        float v = wmax[tid];
        #pragma unroll
        for (int o = 4; o > 0; o >>= 1)
            v = fmaxf(v, __shfl_xor_sync(0x000000FFu, v, o));
        if (tid == 0) g_bmax[b * NCHUNK + c] = v;
    }
}

// ---------------------------------------------------------------------------
// Kernel 3: final reduce over NCHUNK partials per batch, divide by win.
// ---------------------------------------------------------------------------
__global__ void __launch_bounds__(32)
final_kernel(float* __restrict__ out, const int* __restrict__ win_ptr)
{
    const int t = threadIdx.x;
    const float win = (float)(*win_ptr);
    if (t < PB) {
        float m = -INFINITY;
        #pragma unroll
        for (int j = 0; j < NCHUNK; j++)
            m = fmaxf(m, g_bmax[t * NCHUNK + j]);
        out[t] = m / win;
    }
}

// ---------------------------------------------------------------------------
// Launch: inputs in order x, mask, W, b, window_size
// ---------------------------------------------------------------------------
extern "C" void kernel_launch(void* const* d_in, const int* in_sizes, int n_in,
                              void* d_out, int out_size)
{
    const float*        x    = (const float*)d_in[0];
    const unsigned int* mask = (const unsigned int*)d_in[1];
    const float*        W    = (const float*)d_in[2];
    const float*        bias = (const float*)d_in[3];
    const int*          win  = (const int*)d_in[4];
    float* out = (float*)d_out;

    dot_mask_kernel<<<GRID1, 256>>>(x, mask, W, bias);

    dim3 g2(NCHUNK, PB);
    wmax_partial_kernel<<<g2, 256>>>(win);

    final_kernel<<<1, 32>>>(out, win);
}